// round 6
// baseline (speedup 1.0000x reference)
#include <cuda_runtime.h>
#include <cuda_fp16.h>
#include <cstdint>

// ---------------------------------------------------------------------------
// GIN layer:  out = BN( MLP( x + scatter_sum(x[src] -> dst) ) ) + x
// Round 6: fp16 neighbor gather (halves k_agg L2 traffic), x4-unrolled MLP;
//   fp16 HMMA GEMMs (fp32 accumulate) at the legacy issue floor;
//   BN stats fused in GEMM2 epilogue; deterministic everywhere.
// ---------------------------------------------------------------------------

#define DIM 512
#define NMAX 10000
#define EMAX 160000
#define PARTS 80   // ceil(10000/128) = 79 used

typedef __half fp16;

// ---- scratch (device globals; no allocations allowed) ----
__device__ int g_deg[NMAX];
__device__ int g_off[NMAX];
__device__ int g_cur[NMAX];
__device__ int g_csr[EMAX];

__device__ __align__(16) fp16 g_xh[NMAX * DIM];   // fp16 copy of x
__device__ __align__(16) fp16 g_h0[NMAX * DIM];
__device__ __align__(16) fp16 g_h1[NMAX * DIM];
__device__ __align__(16) fp16 g_wt1[DIM * DIM];   // transposed: [n][k]
__device__ __align__(16) fp16 g_wt2[DIM * DIM];
__device__ __align__(16) float g_h2[NMAX * DIM];

__device__ __align__(16) float g_parts[PARTS][DIM];
__device__ __align__(16) float g_partq[PARTS][DIM];
__device__ __align__(16) float g_scale[DIM];
__device__ __align__(16) float g_shift[DIM];

// ---------------------------------------------------------------------------
// helpers
// ---------------------------------------------------------------------------
__device__ __forceinline__ void mma_f16(float* d, const unsigned* a, const unsigned* b) {
    asm volatile(
        "mma.sync.aligned.m16n8k16.row.col.f32.f16.f16.f32 "
        "{%0,%1,%2,%3}, {%4,%5,%6,%7}, {%8,%9}, {%0,%1,%2,%3};\n"
        : "+f"(d[0]), "+f"(d[1]), "+f"(d[2]), "+f"(d[3])
        : "r"(a[0]), "r"(a[1]), "r"(a[2]), "r"(a[3]), "r"(b[0]), "r"(b[1]));
}

__device__ __forceinline__ void ldsm4(unsigned* r, uint32_t saddr) {
    asm volatile(
        "ldmatrix.sync.aligned.m8n8.x4.shared.b16 {%0,%1,%2,%3}, [%4];\n"
        : "=r"(r[0]), "=r"(r[1]), "=r"(r[2]), "=r"(r[3])
        : "r"(saddr));
}

__device__ __forceinline__ void cp16(uint32_t saddr, const void* gaddr, int srcsize) {
    asm volatile("cp.async.cg.shared.global [%0], [%1], 16, %2;\n"
                 :: "r"(saddr), "l"(gaddr), "r"(srcsize));
}
__device__ __forceinline__ void cp_commit() {
    asm volatile("cp.async.commit_group;\n" ::: "memory");
}
__device__ __forceinline__ void cp_wait2() {
    asm volatile("cp.async.wait_group 2;\n" ::: "memory");
}

__device__ __forceinline__ void acc_half4(float4& a, uint2 v) {
    __half2 h01 = *(__half2*)&v.x;
    __half2 h23 = *(__half2*)&v.y;
    float2 f01 = __half22float2(h01);
    float2 f23 = __half22float2(h23);
    a.x += f01.x; a.y += f01.y; a.z += f23.x; a.w += f23.y;
}

// ---------------------------------------------------------------------------
// prep: weight convert (fp16, transposed) + x->fp16 + zero deg, one launch
// grid covers n*DIM/2 threads (half2 per thread)
// ---------------------------------------------------------------------------
__global__ void k_prep(const float* __restrict__ W1, const float* __restrict__ W2,
                       const float* __restrict__ x, int n) {
    int i = blockIdx.x * blockDim.x + threadIdx.x;
    if (i < n) g_deg[i] = 0;
    if (i < DIM * DIM) {
        int k = i / DIM, nn = i % DIM;
        g_wt1[nn * DIM + k] = __float2half_rn(W1[i]);
        g_wt2[nn * DIM + k] = __float2half_rn(W2[i]);
    }
    if (i < n * (DIM / 2)) {
        float2 v = ((const float2*)x)[i];
        ((__half2*)g_xh)[i] = __halves2half2(__float2half_rn(v.x), __float2half_rn(v.y));
    }
}

__global__ void k_hist(const int* __restrict__ dst, int e) {
    int i = blockIdx.x * blockDim.x + threadIdx.x;
    if (i < e) atomicAdd(&g_deg[dst[i]], 1);
}

__global__ void k_scan(int n) {
    __shared__ int wsum[32];
    __shared__ int s_carry;
    int tid = threadIdx.x, lane = tid & 31, w = tid >> 5;
    if (tid == 0) s_carry = 0;
    __syncthreads();
    for (int base = 0; base < n; base += 1024) {
        int idx = base + tid;
        int v = (idx < n) ? g_deg[idx] : 0;
        int xv = v;
        #pragma unroll
        for (int o = 1; o < 32; o <<= 1) {
            int y = __shfl_up_sync(0xffffffffu, xv, o);
            if (lane >= o) xv += y;
        }
        if (lane == 31) wsum[w] = xv;
        __syncthreads();
        if (w == 0) {
            int s = wsum[lane];
            #pragma unroll
            for (int o = 1; o < 32; o <<= 1) {
                int y = __shfl_up_sync(0xffffffffu, s, o);
                if (lane >= o) s += y;
            }
            wsum[lane] = s;
        }
        __syncthreads();
        int incl = xv + (w > 0 ? wsum[w - 1] : 0);
        int excl = incl - v + s_carry;
        if (idx < n) { g_off[idx] = excl; g_cur[idx] = excl; }
        int total = wsum[31];
        __syncthreads();
        if (tid == 0) s_carry += total;
        __syncthreads();
    }
}

__global__ void k_fill(const int* __restrict__ src, const int* __restrict__ dst, int e) {
    int i = blockIdx.x * blockDim.x + threadIdx.x;
    if (i < e) {
        int p = atomicAdd(&g_cur[dst[i]], 1);
        g_csr[p] = src[i];
    }
}

// aggregation: h0[i] = fp16( x[i] + sum_{j in N(i)} xh[j] ), fp32 accumulate.
// Neighbors sorted (deterministic); gather unrolled x4 for MLP.
__global__ void __launch_bounds__(128) k_agg(const float* __restrict__ x, int n) {
    __shared__ int nb[1024];
    int i = blockIdx.x;
    int t = threadIdx.x;
    const float4* x4 = (const float4*)x;
    const uint2* xh = (const uint2*)g_xh;   // 4 halves per thread-column
    float4 acc = x4[(size_t)i * 128 + t];   // self in fp32
    int s = g_off[i];
    int dcount = g_deg[i];

    if (dcount > 1024) {  // unreachable at these sizes; safe fallback
        for (int base = 0; base < dcount; base += 1024) {
            int cnt = min(1024, dcount - base);
            __syncthreads();
            for (int u = t; u < cnt; u += 128) nb[u] = g_csr[s + base + u];
            __syncthreads();
            for (int u = 0; u < cnt; u++) acc_half4(acc, xh[(size_t)nb[u] * 128 + t]);
        }
    } else {
        for (int u = t; u < dcount; u += 128) nb[u] = g_csr[s + u];
        __syncthreads();
        if (dcount <= 32) {
            if (t < 32) {   // warp bitonic sort -> deterministic order
                int v = (t < dcount) ? nb[t] : 0x7fffffff;
                #pragma unroll
                for (int k = 2; k <= 32; k <<= 1) {
                    #pragma unroll
                    for (int j = k >> 1; j > 0; j >>= 1) {
                        int p = __shfl_xor_sync(0xffffffffu, v, j);
                        bool up = ((t & k) == 0);
                        bool takemin = (((t & j) == 0) == up);
                        v = takemin ? min(v, p) : max(v, p);
                    }
                }
                if (t < dcount) nb[t] = v;
            }
        } else if (t == 0) {   // rare tail
            for (int a = 1; a < dcount; a++) {
                int key = nb[a];
                int b = a - 1;
                while (b >= 0 && nb[b] > key) { nb[b + 1] = nb[b]; b--; }
                nb[b + 1] = key;
            }
        }
        __syncthreads();

        float4 a0 = make_float4(0, 0, 0, 0), a1 = a0, a2 = a0, a3 = a0;
        int u = 0;
        for (; u + 4 <= dcount; u += 4) {
            uint2 v0 = xh[(size_t)nb[u + 0] * 128 + t];
            uint2 v1 = xh[(size_t)nb[u + 1] * 128 + t];
            uint2 v2 = xh[(size_t)nb[u + 2] * 128 + t];
            uint2 v3 = xh[(size_t)nb[u + 3] * 128 + t];
            acc_half4(a0, v0); acc_half4(a1, v1);
            acc_half4(a2, v2); acc_half4(a3, v3);
        }
        for (; u < dcount; ++u) acc_half4(a0, xh[(size_t)nb[u] * 128 + t]);
        // fixed combine order (deterministic)
        a0.x += a1.x; a0.y += a1.y; a0.z += a1.z; a0.w += a1.w;
        a2.x += a3.x; a2.y += a3.y; a2.z += a3.z; a2.w += a3.w;
        a0.x += a2.x; a0.y += a2.y; a0.z += a2.z; a0.w += a2.w;
        acc.x += a0.x; acc.y += a0.y; acc.z += a0.z; acc.w += a0.w;
    }

    size_t base = (size_t)i * DIM + (size_t)t * 4;
    __half2 h01 = __halves2half2(__float2half_rn(acc.x), __float2half_rn(acc.y));
    __half2 h23 = __halves2half2(__float2half_rn(acc.z), __float2half_rn(acc.w));
    *(__half2*)(g_h0 + base)     = h01;
    *(__half2*)(g_h0 + base + 2) = h23;
}

// ---------------------------------------------------------------------------
// GEMM: C[M,512] = A[M,512] * W[512,512] (+bias), fp16 HMMA, fp32 accum.
//   4-stage cp.async pipeline. BM=128, BN=128, BK=32; 8 warps, warp tile 64x32.
//   EPI==1: A=h0, B=wt1, epilogue bias+relu -> g_h1 (fp16)
//   EPI==0: A=h1, B=wt2, epilogue bias -> g_h2 fp32 + fused BN partial stats
// ---------------------------------------------------------------------------
#define NCHUNK 16              // 512 / BK(32)
#define ROWB 80                // bytes per smem row (64B data + 16B pad)
#define ARR_BYTES (128 * ROWB) // 10240
#define OFF_A 0
#define OFF_B ARR_BYTES
#define STAGE_BYTES (2 * ARR_BYTES)   // 20480
#define GEMM_SMEM (4 * STAGE_BYTES)   // 81920

template <int EPI>
__global__ void __launch_bounds__(256) k_gemm(const float* __restrict__ bias, int M) {
    extern __shared__ __align__(128) char sm[];

    const fp16* __restrict__ A = (EPI == 1) ? g_h0 : g_h1;
    const fp16* __restrict__ B = (EPI == 1) ? g_wt1 : g_wt2;

    const int t = threadIdx.x;
    const int m0 = blockIdx.y * 128;
    const int n0 = blockIdx.x * 128;
    const int lr = t >> 1, seg = t & 1;
    const int lane = t & 31, wid = t >> 5;
    const int wm = (wid >> 2) * 64;
    const int wn = (wid & 3) * 32;
    const uint32_t smbase = (uint32_t)__cvta_generic_to_shared(sm);

    const int arow = m0 + lr;
    const int apred = (arow < M) ? 16 : 0;
    const uint32_t s_off = (uint32_t)(lr * ROWB + seg * 32);
    const fp16* gA = A + (size_t)arow * 512 + seg * 16;
    const fp16* gB = B + (size_t)(n0 + lr) * 512 + seg * 16;

    #define LOAD_CHUNK(c) do {                                                \
        uint32_t _sb = smbase + ((c) & 3) * STAGE_BYTES + s_off;              \
        int _k0 = (c) * 32;                                                   \
        cp16(_sb + OFF_A,      gA + _k0,     apred);                          \
        cp16(_sb + OFF_A + 16, gA + _k0 + 8, apred);                          \
        cp16(_sb + OFF_B,      gB + _k0,     16);                             \
        cp16(_sb + OFF_B + 16, gB + _k0 + 8, 16);                             \
    } while (0)

    float acc[4][4][4];
    #pragma unroll
    for (int a = 0; a < 4; a++)
        #pragma unroll
        for (int b = 0; b < 4; b++)
            #pragma unroll
            for (int c = 0; c < 4; c++) acc[a][b][c] = 0.f;

    LOAD_CHUNK(0); cp_commit();
    LOAD_CHUNK(1); cp_commit();
    LOAD_CHUNK(2); cp_commit();

    for (int c = 0; c < NCHUNK; ++c) {
        cp_wait2();
        __syncthreads();
        if (c + 3 < NCHUNK) LOAD_CHUNK(c + 3);
        cp_commit();

        const uint32_t sb = smbase + (c & 3) * STAGE_BYTES;
        #pragma unroll
        for (int kk = 0; kk < 32; kk += 16) {
            unsigned bfr[4][2];
            #pragma unroll
            for (int g = 0; g < 2; g++) {
                int nr = wn + g * 16 + (lane & 7) + ((lane & 16) ? 8 : 0);
                int kc = kk + ((lane & 8) ? 8 : 0);
                unsigned r[4];
                ldsm4(r, sb + OFF_B + nr * ROWB + kc * 2);
                bfr[g*2][0] = r[0]; bfr[g*2][1] = r[1];
                bfr[g*2+1][0] = r[2]; bfr[g*2+1][1] = r[3];
            }
            #pragma unroll
            for (int mf = 0; mf < 4; mf++) {
                int ar = wm + mf * 16 + (lane & 15);
                int ac = kk + ((lane >> 4) << 3);
                unsigned ah[4];
                ldsm4(ah, sb + OFF_A + ar * ROWB + ac * 2);
                #pragma unroll
                for (int nf = 0; nf < 4; nf++) {
                    mma_f16(acc[mf][nf], ah, bfr[nf]);
                }
            }
        }
    }

    // ---- epilogue ----
    float csum[4][2], csq[4][2];
    if (EPI == 0) {
        #pragma unroll
        for (int nf = 0; nf < 4; nf++) { csum[nf][0] = csum[nf][1] = 0.f;
                                         csq[nf][0] = csq[nf][1] = 0.f; }
    }

    #pragma unroll
    for (int mf = 0; mf < 4; mf++) {
        #pragma unroll
        for (int nf = 0; nf < 4; nf++) {
            int col = n0 + wn + nf * 8 + (lane & 3) * 2;
            float b0 = bias[col], b1 = bias[col + 1];
            #pragma unroll
            for (int h = 0; h < 2; h++) {
                int row = m0 + wm + mf * 16 + (lane >> 2) + h * 8;
                if (row < M) {
                    float v0 = acc[mf][nf][h * 2 + 0] + b0;
                    float v1 = acc[mf][nf][h * 2 + 1] + b1;
                    if (EPI == 1) {
                        v0 = fmaxf(v0, 0.f);
                        v1 = fmaxf(v1, 0.f);
                        __half2 hv = __halves2half2(__float2half_rn(v0),
                                                    __float2half_rn(v1));
                        *(__half2*)(g_h1 + (size_t)row * 512 + col) = hv;
                    } else {
                        float2 fv; fv.x = v0; fv.y = v1;
                        *(float2*)(g_h2 + (size_t)row * 512 + col) = fv;
                        csum[nf][0] += v0; csum[nf][1] += v1;
                        csq[nf][0] += v0 * v0; csq[nf][1] += v1 * v1;
                    }
                }
            }
        }
    }

    if (EPI == 0) {
        // deterministic column reduction: shfl stride 16..4, then 2-step smem
        #pragma unroll
        for (int nf = 0; nf < 4; nf++)
            #pragma unroll
            for (int j = 0; j < 2; j++) {
                #pragma unroll
                for (int off = 16; off >= 4; off >>= 1) {
                    csum[nf][j] += __shfl_down_sync(0xffffffffu, csum[nf][j], off);
                    csq[nf][j]  += __shfl_down_sync(0xffffffffu, csq[nf][j], off);
                }
            }
        float* s_red = (float*)sm;
        __syncthreads();
        if (wid < 4 && (lane >> 2) == 0) {
            #pragma unroll
            for (int nf = 0; nf < 4; nf++)
                #pragma unroll
                for (int j = 0; j < 2; j++) {
                    int cit = wn + nf * 8 + (lane & 3) * 2 + j;
                    s_red[cit] = csum[nf][j];
                    s_red[128 + cit] = csq[nf][j];
                }
        }
        __syncthreads();
        if (wid >= 4 && (lane >> 2) == 0) {
            #pragma unroll
            for (int nf = 0; nf < 4; nf++)
                #pragma unroll
                for (int j = 0; j < 2; j++) {
                    int cit = wn + nf * 8 + (lane & 3) * 2 + j;
                    g_parts[blockIdx.y][n0 + cit] = s_red[cit] + csum[nf][j];
                    g_partq[blockIdx.y][n0 + cit] = s_red[128 + cit] + csq[nf][j];
                }
        }
    }
    #undef LOAD_CHUNK
}

// ---------------------------------------------------------------------------
// BN params + output
// ---------------------------------------------------------------------------
__global__ void k_bnparam(const float* __restrict__ gamma, const float* __restrict__ beta,
                          float invn, int nparts) {
    int c = blockIdx.x * blockDim.x + threadIdx.x;
    if (c >= DIM) return;
    float s = 0, q = 0;
    for (int p = 0; p < nparts; p++) { s += g_parts[p][c]; q += g_partq[p][c]; }
    float mean = s * invn;
    float var = q * invn - mean * mean;
    float sc = gamma[c] * rsqrtf(var + 1e-5f);
    g_scale[c] = sc;
    g_shift[c] = beta[c] - mean * sc;
}

__global__ void k_out(const float* __restrict__ x, float* __restrict__ out, int n) {
    int i = blockIdx.x * blockDim.x + threadIdx.x;
    if (i >= n * 128) return;
    int c4 = i & 127;
    float4 h = ((const float4*)g_h2)[i];
    float4 xv = ((const float4*)x)[i];
    float4 sc = ((const float4*)g_scale)[c4];
    float4 sh = ((const float4*)g_shift)[c4];
    float4 o;
    o.x = h.x * sc.x + sh.x + xv.x;
    o.y = h.y * sc.y + sh.y + xv.y;
    o.z = h.z * sc.z + sh.z + xv.z;
    o.w = h.w * sc.w + sh.w + xv.w;
    ((float4*)out)[i] = o;
}

// ---------------------------------------------------------------------------
extern "C" void kernel_launch(void* const* d_in, const int* in_sizes, int n_in,
                              void* d_out, int out_size) {
    const float* x     = (const float*)d_in[0];
    const int*   ei    = (const int*)d_in[1];
    const float* W1    = (const float*)d_in[2];
    const float* b1    = (const float*)d_in[3];
    const float* W2    = (const float*)d_in[4];
    const float* b2    = (const float*)d_in[5];
    const float* gamma = (const float*)d_in[6];
    const float* beta  = (const float*)d_in[7];
    float* out = (float*)d_out;

    int n = in_sizes[0] / DIM;
    int e = in_sizes[1] / 2;
    const int* src = ei;
    const int* dst = ei + e;

    static bool attr_set = false;
    if (!attr_set) {
        cudaFuncSetAttribute(k_gemm<1>, cudaFuncAttributeMaxDynamicSharedMemorySize, GEMM_SMEM);
        cudaFuncSetAttribute(k_gemm<0>, cudaFuncAttributeMaxDynamicSharedMemorySize, GEMM_SMEM);
        attr_set = true;
    }

    int prep_threads = n * (DIM / 2);       // covers x-convert, weights, deg zero
    k_prep<<<(prep_threads + 255) / 256, 256>>>(W1, W2, x, n);
    k_hist<<<(e + 255) / 256, 256>>>(dst, e);
    k_scan<<<1, 1024>>>(n);
    k_fill<<<(e + 255) / 256, 256>>>(src, dst, e);
    k_agg<<<n, 128>>>(x, n);

    int gy = (n + 127) / 128;               // 79
    dim3 gg(4, gy);
    k_gemm<1><<<gg, 256, GEMM_SMEM>>>(b1, n);
    k_gemm<0><<<gg, 256, GEMM_SMEM>>>(b2, n);

    k_bnparam<<<2, 256>>>(gamma, beta, 1.0f / (float)n, gy);
    k_out<<<(n * 128 + 255) / 256, 256>>>(x, out, n);
}

// round 7
// speedup vs baseline: 1.1145x; 1.1145x over previous
#include <cuda_runtime.h>
#include <cuda_fp16.h>
#include <cstdint>

// ---------------------------------------------------------------------------
// GIN layer:  out = BN( MLP( x + scatter_sum(x[src] -> dst) ) ) + x
// Round 7: revert fp16-gather regression (fp32 float4 gather, x4 unroll);
//   BM=64 GEMM tiles (628 CTAs, 3 CTAs/SM) to kill wave-quantization tail;
//   fp16 HMMA fp32-accum, 4-stage cp.async; BN stats fused in GEMM2 epilogue.
// ---------------------------------------------------------------------------

#define DIM 512
#define NMAX 10000
#define EMAX 160000
#define PARTS 160   // ceil(10000/64) = 157 used

typedef __half fp16;

// ---- scratch (device globals; no allocations allowed) ----
__device__ int g_deg[NMAX];
__device__ int g_off[NMAX];
__device__ int g_cur[NMAX];
__device__ int g_csr[EMAX];

__device__ __align__(16) fp16 g_h0[NMAX * DIM];
__device__ __align__(16) fp16 g_h1[NMAX * DIM];
__device__ __align__(16) fp16 g_wt1[DIM * DIM];   // transposed: [n][k]
__device__ __align__(16) fp16 g_wt2[DIM * DIM];
__device__ __align__(16) float g_h2[NMAX * DIM];

__device__ __align__(16) float g_parts[PARTS][DIM];
__device__ __align__(16) float g_partq[PARTS][DIM];
__device__ __align__(16) float g_scale[DIM];
__device__ __align__(16) float g_shift[DIM];

// ---------------------------------------------------------------------------
// helpers
// ---------------------------------------------------------------------------
__device__ __forceinline__ void mma_f16(float* d, const unsigned* a, const unsigned* b) {
    asm volatile(
        "mma.sync.aligned.m16n8k16.row.col.f32.f16.f16.f32 "
        "{%0,%1,%2,%3}, {%4,%5,%6,%7}, {%8,%9}, {%0,%1,%2,%3};\n"
        : "+f"(d[0]), "+f"(d[1]), "+f"(d[2]), "+f"(d[3])
        : "r"(a[0]), "r"(a[1]), "r"(a[2]), "r"(a[3]), "r"(b[0]), "r"(b[1]));
}

__device__ __forceinline__ void ldsm4(unsigned* r, uint32_t saddr) {
    asm volatile(
        "ldmatrix.sync.aligned.m8n8.x4.shared.b16 {%0,%1,%2,%3}, [%4];\n"
        : "=r"(r[0]), "=r"(r[1]), "=r"(r[2]), "=r"(r[3])
        : "r"(saddr));
}

__device__ __forceinline__ void cp16(uint32_t saddr, const void* gaddr, int srcsize) {
    asm volatile("cp.async.cg.shared.global [%0], [%1], 16, %2;\n"
                 :: "r"(saddr), "l"(gaddr), "r"(srcsize));
}
__device__ __forceinline__ void cp_commit() {
    asm volatile("cp.async.commit_group;\n" ::: "memory");
}
__device__ __forceinline__ void cp_wait2() {
    asm volatile("cp.async.wait_group 2;\n" ::: "memory");
}

// ---------------------------------------------------------------------------
// prep kernels (R5 versions)
// ---------------------------------------------------------------------------
__global__ void k_wconv(const float* __restrict__ W1, const float* __restrict__ W2, int n) {
    int i = blockIdx.x * blockDim.x + threadIdx.x;
    if (i < n) g_deg[i] = 0;
    if (i >= DIM * DIM) return;
    int k = i / DIM, nn = i % DIM;
    g_wt1[nn * DIM + k] = __float2half_rn(W1[i]);
    g_wt2[nn * DIM + k] = __float2half_rn(W2[i]);
}

__global__ void k_hist(const int* __restrict__ dst, int e) {
    int i = blockIdx.x * blockDim.x + threadIdx.x;
    if (i < e) atomicAdd(&g_deg[dst[i]], 1);
}

__global__ void k_scan(int n) {
    __shared__ int wsum[32];
    __shared__ int s_carry;
    int tid = threadIdx.x, lane = tid & 31, w = tid >> 5;
    if (tid == 0) s_carry = 0;
    __syncthreads();
    for (int base = 0; base < n; base += 1024) {
        int idx = base + tid;
        int v = (idx < n) ? g_deg[idx] : 0;
        int xv = v;
        #pragma unroll
        for (int o = 1; o < 32; o <<= 1) {
            int y = __shfl_up_sync(0xffffffffu, xv, o);
            if (lane >= o) xv += y;
        }
        if (lane == 31) wsum[w] = xv;
        __syncthreads();
        if (w == 0) {
            int s = wsum[lane];
            #pragma unroll
            for (int o = 1; o < 32; o <<= 1) {
                int y = __shfl_up_sync(0xffffffffu, s, o);
                if (lane >= o) s += y;
            }
            wsum[lane] = s;
        }
        __syncthreads();
        int incl = xv + (w > 0 ? wsum[w - 1] : 0);
        int excl = incl - v + s_carry;
        if (idx < n) { g_off[idx] = excl; g_cur[idx] = excl; }
        int total = wsum[31];
        __syncthreads();
        if (tid == 0) s_carry += total;
        __syncthreads();
    }
}

__global__ void k_fill(const int* __restrict__ src, const int* __restrict__ dst, int e) {
    int i = blockIdx.x * blockDim.x + threadIdx.x;
    if (i < e) {
        int p = atomicAdd(&g_cur[dst[i]], 1);
        g_csr[p] = src[i];
    }
}

// aggregation: h0[i] = fp16( x[i] + sum_{j in N(i)} x[j] ), fp32 gather (R5),
// x4 unroll with fixed combine order (deterministic).
__global__ void __launch_bounds__(128) k_agg(const float* __restrict__ x, int n) {
    __shared__ int nb[1024];
    int i = blockIdx.x;
    int t = threadIdx.x;
    const float4* x4 = (const float4*)x;
    float4 acc = x4[(size_t)i * 128 + t];
    int s = g_off[i];
    int dcount = g_deg[i];

    if (dcount > 1024) {  // unreachable at these sizes; safe fallback
        for (int base = 0; base < dcount; base += 1024) {
            int cnt = min(1024, dcount - base);
            __syncthreads();
            for (int u = t; u < cnt; u += 128) nb[u] = g_csr[s + base + u];
            __syncthreads();
            for (int u = 0; u < cnt; u++) {
                float4 v = x4[(size_t)nb[u] * 128 + t];
                acc.x += v.x; acc.y += v.y; acc.z += v.z; acc.w += v.w;
            }
        }
    } else {
        for (int u = t; u < dcount; u += 128) nb[u] = g_csr[s + u];
        __syncthreads();
        if (dcount <= 32) {
            if (t < 32) {   // warp bitonic sort -> deterministic order
                int v = (t < dcount) ? nb[t] : 0x7fffffff;
                #pragma unroll
                for (int k = 2; k <= 32; k <<= 1) {
                    #pragma unroll
                    for (int j = k >> 1; j > 0; j >>= 1) {
                        int p = __shfl_xor_sync(0xffffffffu, v, j);
                        bool up = ((t & k) == 0);
                        bool takemin = (((t & j) == 0) == up);
                        v = takemin ? min(v, p) : max(v, p);
                    }
                }
                if (t < dcount) nb[t] = v;
            }
        } else if (t == 0) {   // rare tail
            for (int a = 1; a < dcount; a++) {
                int key = nb[a];
                int b = a - 1;
                while (b >= 0 && nb[b] > key) { nb[b + 1] = nb[b]; b--; }
                nb[b + 1] = key;
            }
        }
        __syncthreads();

        float4 a0 = make_float4(0, 0, 0, 0), a1 = a0, a2 = a0, a3 = a0;
        int u = 0;
        for (; u + 4 <= dcount; u += 4) {
            float4 v0 = x4[(size_t)nb[u + 0] * 128 + t];
            float4 v1 = x4[(size_t)nb[u + 1] * 128 + t];
            float4 v2 = x4[(size_t)nb[u + 2] * 128 + t];
            float4 v3 = x4[(size_t)nb[u + 3] * 128 + t];
            a0.x += v0.x; a0.y += v0.y; a0.z += v0.z; a0.w += v0.w;
            a1.x += v1.x; a1.y += v1.y; a1.z += v1.z; a1.w += v1.w;
            a2.x += v2.x; a2.y += v2.y; a2.z += v2.z; a2.w += v2.w;
            a3.x += v3.x; a3.y += v3.y; a3.z += v3.z; a3.w += v3.w;
        }
        for (; u < dcount; ++u) {
            float4 v = x4[(size_t)nb[u] * 128 + t];
            a0.x += v.x; a0.y += v.y; a0.z += v.z; a0.w += v.w;
        }
        a0.x += a1.x; a0.y += a1.y; a0.z += a1.z; a0.w += a1.w;
        a2.x += a3.x; a2.y += a3.y; a2.z += a3.z; a2.w += a3.w;
        a0.x += a2.x; a0.y += a2.y; a0.z += a2.z; a0.w += a2.w;
        acc.x += a0.x; acc.y += a0.y; acc.z += a0.z; acc.w += a0.w;
    }

    size_t base = (size_t)i * DIM + (size_t)t * 4;
    __half2 h01 = __halves2half2(__float2half_rn(acc.x), __float2half_rn(acc.y));
    __half2 h23 = __halves2half2(__float2half_rn(acc.z), __float2half_rn(acc.w));
    *(__half2*)(g_h0 + base)     = h01;
    *(__half2*)(g_h0 + base + 2) = h23;
}

// ---------------------------------------------------------------------------
// GEMM: C[M,512] = A[M,512] * W[512,512] (+bias), fp16 HMMA, fp32 accum.
//   BM=64, BN=128, BK=32; 8 warps (2x4), warp tile 32x32; 4-stage cp.async.
//   EPI==1: A=h0, B=wt1, epilogue bias+relu -> g_h1 (fp16)
//   EPI==0: A=h1, B=wt2, epilogue bias -> g_h2 fp32 + fused BN partial stats
// ---------------------------------------------------------------------------
#define BM 64
#define NCHUNK 16              // 512 / BK(32)
#define ROWB 80                // bytes per smem row (64B data + 16B pad)
#define A_BYTES (BM * ROWB)    // 5120
#define B_BYTES (128 * ROWB)   // 10240
#define OFF_A 0
#define OFF_B A_BYTES
#define STAGE_BYTES (A_BYTES + B_BYTES)  // 15360
#define GEMM_SMEM (4 * STAGE_BYTES)      // 61440

template <int EPI>
__global__ void __launch_bounds__(256) k_gemm(const float* __restrict__ bias, int M) {
    extern __shared__ __align__(128) char sm[];

    const fp16* __restrict__ A = (EPI == 1) ? g_h0 : g_h1;
    const fp16* __restrict__ B = (EPI == 1) ? g_wt1 : g_wt2;

    const int t = threadIdx.x;
    const int m0 = blockIdx.y * BM;
    const int n0 = blockIdx.x * 128;
    const int lane = t & 31, wid = t >> 5;
    const int wm = (wid >> 2) * 32;     // 2 warp rows
    const int wn = (wid & 3) * 32;      // 4 warp cols
    const uint32_t smbase = (uint32_t)__cvta_generic_to_shared(sm);

    // A loader: row = t>>2 (64 rows), 16B segment = t&3
    const int a_r = t >> 2, a_s = t & 3;
    const int arow = m0 + a_r;
    const int apred = (arow < M) ? 16 : 0;
    const uint32_t sA_off = (uint32_t)(a_r * ROWB + a_s * 16);
    const fp16* gA = A + (size_t)arow * 512 + a_s * 8;
    // B loader: row = t>>1 (128 rows), 32B segment = t&1
    const int b_r = t >> 1, b_s = t & 1;
    const uint32_t sB_off = (uint32_t)(b_r * ROWB + b_s * 32);
    const fp16* gB = B + (size_t)(n0 + b_r) * 512 + b_s * 16;

    #define LOAD_CHUNK(c) do {                                                \
        uint32_t _sb = smbase + ((c) & 3) * STAGE_BYTES;                      \
        int _k0 = (c) * 32;                                                   \
        cp16(_sb + OFF_A + sA_off, gA + _k0,     apred);                      \
        cp16(_sb + OFF_B + sB_off,      gB + _k0,     16);                    \
        cp16(_sb + OFF_B + sB_off + 16, gB + _k0 + 8, 16);                    \
    } while (0)

    float acc[2][4][4];
    #pragma unroll
    for (int a = 0; a < 2; a++)
        #pragma unroll
        for (int b = 0; b < 4; b++)
            #pragma unroll
            for (int c = 0; c < 4; c++) acc[a][b][c] = 0.f;

    LOAD_CHUNK(0); cp_commit();
    LOAD_CHUNK(1); cp_commit();
    LOAD_CHUNK(2); cp_commit();

    for (int c = 0; c < NCHUNK; ++c) {
        cp_wait2();
        __syncthreads();
        if (c + 3 < NCHUNK) LOAD_CHUNK(c + 3);
        cp_commit();

        const uint32_t sb = smbase + (c & 3) * STAGE_BYTES;
        #pragma unroll
        for (int kk = 0; kk < 32; kk += 16) {
            unsigned bfr[4][2];
            #pragma unroll
            for (int g = 0; g < 2; g++) {
                int nr = wn + g * 16 + (lane & 7) + ((lane & 16) ? 8 : 0);
                int kc = kk + ((lane & 8) ? 8 : 0);
                unsigned r[4];
                ldsm4(r, sb + OFF_B + nr * ROWB + kc * 2);
                bfr[g*2][0] = r[0]; bfr[g*2][1] = r[1];
                bfr[g*2+1][0] = r[2]; bfr[g*2+1][1] = r[3];
            }
            #pragma unroll
            for (int mf = 0; mf < 2; mf++) {
                int ar = wm + mf * 16 + (lane & 15);
                int ac = kk + ((lane >> 4) << 3);
                unsigned ah[4];
                ldsm4(ah, sb + OFF_A + ar * ROWB + ac * 2);
                #pragma unroll
                for (int nf = 0; nf < 4; nf++) {
                    mma_f16(acc[mf][nf], ah, bfr[nf]);
                }
            }
        }
    }

    // ---- epilogue ----
    float csum[4][2], csq[4][2];
    if (EPI == 0) {
        #pragma unroll
        for (int nf = 0; nf < 4; nf++) { csum[nf][0] = csum[nf][1] = 0.f;
                                         csq[nf][0] = csq[nf][1] = 0.f; }
    }

    #pragma unroll
    for (int mf = 0; mf < 2; mf++) {
        #pragma unroll
        for (int nf = 0; nf < 4; nf++) {
            int col = n0 + wn + nf * 8 + (lane & 3) * 2;
            float b0 = bias[col], b1 = bias[col + 1];
            #pragma unroll
            for (int h = 0; h < 2; h++) {
                int row = m0 + wm + mf * 16 + (lane >> 2) + h * 8;
                if (row < M) {
                    float v0 = acc[mf][nf][h * 2 + 0] + b0;
                    float v1 = acc[mf][nf][h * 2 + 1] + b1;
                    if (EPI == 1) {
                        v0 = fmaxf(v0, 0.f);
                        v1 = fmaxf(v1, 0.f);
                        __half2 hv = __halves2half2(__float2half_rn(v0),
                                                    __float2half_rn(v1));
                        *(__half2*)(g_h1 + (size_t)row * 512 + col) = hv;
                    } else {
                        float2 fv; fv.x = v0; fv.y = v1;
                        *(float2*)(g_h2 + (size_t)row * 512 + col) = fv;
                        csum[nf][0] += v0; csum[nf][1] += v1;
                        csq[nf][0] += v0 * v0; csq[nf][1] += v1 * v1;
                    }
                }
            }
        }
    }

    if (EPI == 0) {
        // deterministic column reduction: shfl stride 16..4, then 2-step smem
        #pragma unroll
        for (int nf = 0; nf < 4; nf++)
            #pragma unroll
            for (int j = 0; j < 2; j++) {
                #pragma unroll
                for (int off = 16; off >= 4; off >>= 1) {
                    csum[nf][j] += __shfl_down_sync(0xffffffffu, csum[nf][j], off);
                    csq[nf][j]  += __shfl_down_sync(0xffffffffu, csq[nf][j], off);
                }
            }
        float* s_red = (float*)sm;
        __syncthreads();
        if (wid < 4 && (lane >> 2) == 0) {
            #pragma unroll
            for (int nf = 0; nf < 4; nf++)
                #pragma unroll
                for (int j = 0; j < 2; j++) {
                    int cit = wn + nf * 8 + (lane & 3) * 2 + j;
                    s_red[cit] = csum[nf][j];
                    s_red[128 + cit] = csq[nf][j];
                }
        }
        __syncthreads();
        if (wid >= 4 && (lane >> 2) == 0) {
            #pragma unroll
            for (int nf = 0; nf < 4; nf++)
                #pragma unroll
                for (int j = 0; j < 2; j++) {
                    int cit = wn + nf * 8 + (lane & 3) * 2 + j;
                    g_parts[blockIdx.y][n0 + cit] = s_red[cit] + csum[nf][j];
                    g_partq[blockIdx.y][n0 + cit] = s_red[128 + cit] + csq[nf][j];
                }
        }
    }
    #undef LOAD_CHUNK
}

// ---------------------------------------------------------------------------
// BN params + output
// ---------------------------------------------------------------------------
__global__ void k_bnparam(const float* __restrict__ gamma, const float* __restrict__ beta,
                          float invn, int nparts) {
    int c = blockIdx.x * blockDim.x + threadIdx.x;
    if (c >= DIM) return;
    float s = 0, q = 0;
    for (int p = 0; p < nparts; p++) { s += g_parts[p][c]; q += g_partq[p][c]; }
    float mean = s * invn;
    float var = q * invn - mean * mean;
    float sc = gamma[c] * rsqrtf(var + 1e-5f);
    g_scale[c] = sc;
    g_shift[c] = beta[c] - mean * sc;
}

__global__ void k_out(const float* __restrict__ x, float* __restrict__ out, int n) {
    int i = blockIdx.x * blockDim.x + threadIdx.x;
    if (i >= n * 128) return;
    int c4 = i & 127;
    float4 h = ((const float4*)g_h2)[i];
    float4 xv = ((const float4*)x)[i];
    float4 sc = ((const float4*)g_scale)[c4];
    float4 sh = ((const float4*)g_shift)[c4];
    float4 o;
    o.x = h.x * sc.x + sh.x + xv.x;
    o.y = h.y * sc.y + sh.y + xv.y;
    o.z = h.z * sc.z + sh.z + xv.z;
    o.w = h.w * sc.w + sh.w + xv.w;
    ((float4*)out)[i] = o;
}

// ---------------------------------------------------------------------------
extern "C" void kernel_launch(void* const* d_in, const int* in_sizes, int n_in,
                              void* d_out, int out_size) {
    const float* x     = (const float*)d_in[0];
    const int*   ei    = (const int*)d_in[1];
    const float* W1    = (const float*)d_in[2];
    const float* b1    = (const float*)d_in[3];
    const float* W2    = (const float*)d_in[4];
    const float* b2    = (const float*)d_in[5];
    const float* gamma = (const float*)d_in[6];
    const float* beta  = (const float*)d_in[7];
    float* out = (float*)d_out;

    int n = in_sizes[0] / DIM;
    int e = in_sizes[1] / 2;
    const int* src = ei;
    const int* dst = ei + e;

    static bool attr_set = false;
    if (!attr_set) {
        cudaFuncSetAttribute(k_gemm<1>, cudaFuncAttributeMaxDynamicSharedMemorySize, GEMM_SMEM);
        cudaFuncSetAttribute(k_gemm<0>, cudaFuncAttributeMaxDynamicSharedMemorySize, GEMM_SMEM);
        attr_set = true;
    }

    k_wconv<<<(DIM * DIM + 255) / 256, 256>>>(W1, W2, n);
    k_hist<<<(e + 255) / 256, 256>>>(dst, e);
    k_scan<<<1, 1024>>>(n);
    k_fill<<<(e + 255) / 256, 256>>>(src, dst, e);
    k_agg<<<n, 128>>>(x, n);

    int gy = (n + BM - 1) / BM;             // 157
    dim3 gg(4, gy);
    k_gemm<1><<<gg, 256, GEMM_SMEM>>>(b1, n);
    k_gemm<0><<<gg, 256, GEMM_SMEM>>>(b2, n);

    k_bnparam<<<2, 256>>>(gamma, beta, 1.0f / (float)n, gy);
    k_out<<<(n * 128 + 255) / 256, 256>>>(x, out, n);
}